// round 17
// baseline (speedup 1.0000x reference)
#include <cuda_runtime.h>
#include <cuda_bf16.h>
#include <cstdint>

// out[b,o] = sigmoid( (x@W + colsum(bias))[b,o] / 1024 )
// R16 best (14.85us) + PDL: epilogue launch/ramp overlaps GEMM execution.
//  - GEMM kernel: griddepcontrol.launch_dependents (early)
//  - epilogue:    griddepcontrol.wait before reading partials
//  - host:        programmatic stream serialization attribute on launch 2

#define BATCH   256
#define INDIM   1024
#define OUTDIM  1024

#define KSPLIT  4
#define KCHUNK  (INDIM / KSPLIT)   // 256
#define BK      32
#define NIT     (KCHUNK / BK)      // 8
#define BM      64
#define BN      64

#define A_STRIDE 40   // bf16 units: 80B rows, ldmatrix conflict-free
#define B_STRIDE 72   // bf16 units: 144B rows
#define A_BUF_BYTES (BM * A_STRIDE * 2)
#define B_BUF_BYTES (BK * B_STRIDE * 2)

// scratch (device globals: no allocation allowed)
__device__ __nv_bfloat16 g_part[KSPLIT][BATCH * OUTDIM];   // 2 MB bf16 partials
__device__ float g_bias_part[KSPLIT][OUTDIM];

__device__ __forceinline__ void ldmatrix_x4(uint32_t* r, uint32_t addr) {
    asm volatile("ldmatrix.sync.aligned.m8n8.x4.shared.b16 {%0,%1,%2,%3}, [%4];"
                 : "=r"(r[0]), "=r"(r[1]), "=r"(r[2]), "=r"(r[3]) : "r"(addr));
}
__device__ __forceinline__ void ldmatrix_x4_trans(uint32_t* r, uint32_t addr) {
    asm volatile("ldmatrix.sync.aligned.m8n8.x4.trans.shared.b16 {%0,%1,%2,%3}, [%4];"
                 : "=r"(r[0]), "=r"(r[1]), "=r"(r[2]), "=r"(r[3]) : "r"(addr));
}
__device__ __forceinline__ void mma_bf16(float* c, const uint32_t* a, uint32_t b0, uint32_t b1) {
    asm volatile("mma.sync.aligned.m16n8k16.row.col.f32.bf16.bf16.f32 "
                 "{%0,%1,%2,%3}, {%4,%5,%6,%7}, {%8,%9}, {%0,%1,%2,%3};"
                 : "+f"(c[0]), "+f"(c[1]), "+f"(c[2]), "+f"(c[3])
                 : "r"(a[0]), "r"(a[1]), "r"(a[2]), "r"(a[3]), "r"(b0), "r"(b1));
}
__device__ __forceinline__ uint32_t pack_bf2(float lo, float hi) {
    __nv_bfloat162 v = __floats2bfloat162_rn(lo, hi);
    return *reinterpret_cast<uint32_t*>(&v);
}
__device__ __forceinline__ void pack_store16(__nv_bfloat16* dst, float4 a, float4 b) {
    uint4 u;
    u.x = pack_bf2(a.x, a.y); u.y = pack_bf2(a.z, a.w);
    u.z = pack_bf2(b.x, b.y); u.w = pack_bf2(b.z, b.w);
    *reinterpret_cast<uint4*>(dst) = u;
}
__device__ __forceinline__ float sigmoidf_(float t) {
    return 1.0f / (1.0f + __expf(-t));
}
__device__ __forceinline__ void pdl_trigger() {
    asm volatile("griddepcontrol.launch_dependents;");
}
__device__ __forceinline__ void pdl_wait() {
    asm volatile("griddepcontrol.wait;" ::: "memory");
}

// ---------------------------------------------------------------------------
// Kernel 1: split-K GEMM partials (bf16) + bias colsum partials.
// grid = (16 n-tiles, 5, 4 k-slices); y<4 => GEMM m-tile, y==4 => bias block.
// Mainloop byte-identical to R16 best.
// ---------------------------------------------------------------------------
__global__ void __launch_bounds__(256) gemm_splitk_kernel(
        const float* __restrict__ x,
        const float* __restrict__ w,
        const float* __restrict__ bias) {
    __shared__ __nv_bfloat16 As[2][BM * A_STRIDE];
    __shared__ __nv_bfloat16 Bs[2][BK * B_STRIDE];
    __shared__ float red[4][BN];

    const int tid = threadIdx.x;
    const int n0  = blockIdx.x * BN;
    const int kz  = blockIdx.z;
    const int k0  = kz * KCHUNK;

    // let the epilogue grid launch + ramp while we compute
    pdl_trigger();

    // ---------------- bias colsum blocks ----------------
    if (blockIdx.y == 4) {
        const int col = tid & 63;
        const int rg  = tid >> 6;            // 4 groups x 64 rows
        const float* bp = bias + (size_t)(k0 + rg * 64) * OUTDIM + n0 + col;
        float s = 0.0f;
        #pragma unroll 16
        for (int r = 0; r < 64; ++r)
            s += __ldg(bp + (size_t)r * OUTDIM);
        red[rg][col] = s;
        __syncthreads();
        if (tid < 64) {
            float t = red[0][tid] + red[1][tid] + red[2][tid] + red[3][tid];
            g_bias_part[kz][n0 + tid] = t;
        }
        return;
    }

    // ---------------- GEMM blocks ----------------
    const int m0   = blockIdx.y * BM;
    const int lane = tid & 31;
    const int wid  = tid >> 5;
    const int wm   = wid >> 2;   // 0..1 -> 32 rows
    const int wn   = wid & 3;    // 0..3 -> 16 cols

    const int arow = tid >> 2;           // 0..63
    const int ak   = (tid & 3) << 3;     // 0,8,16,24
    const int brow = tid >> 3;           // 0..31
    const int bno  = (tid & 7) << 3;     // 0..56

    const float* xg = x + (size_t)(m0 + arow) * INDIM + k0 + ak;
    const float* wg = w + (size_t)(k0 + brow) * OUTDIM + n0 + bno;

    float acc[2][2][4];
    #pragma unroll
    for (int i = 0; i < 2; ++i)
        #pragma unroll
        for (int j = 0; j < 2; ++j)
            #pragma unroll
            for (int c = 0; c < 4; ++c)
                acc[i][j][c] = 0.0f;

    const int lr = lane & 15;
    const int lc = (lane >> 4) << 3;
    uint32_t a_off[2][2], b_off[2];
    #pragma unroll
    for (int mt = 0; mt < 2; ++mt)
        #pragma unroll
        for (int s = 0; s < 2; ++s)
            a_off[mt][s] = ((wm * 32 + mt * 16 + lr) * A_STRIDE + s * 16 + lc) * 2;
    #pragma unroll
    for (int s = 0; s < 2; ++s)
        b_off[s] = ((s * 16 + lr) * B_STRIDE + wn * 16 + lc) * 2;

    const uint32_t As_base = (uint32_t)__cvta_generic_to_shared(&As[0][0]);
    const uint32_t Bs_base = (uint32_t)__cvta_generic_to_shared(&Bs[0][0]);

    // prologue
    float4 aR0 = *(const float4*)(xg);
    float4 aR1 = *(const float4*)(xg + 4);
    float4 bR0 = *(const float4*)(wg);
    float4 bR1 = *(const float4*)(wg + 4);
    pack_store16(&As[0][arow * A_STRIDE + ak], aR0, aR1);
    pack_store16(&Bs[0][brow * B_STRIDE + bno], bR0, bR1);
    __syncthreads();

    #pragma unroll
    for (int it = 0; it < NIT; ++it) {
        const int buf = it & 1;

        if (it + 1 < NIT) {
            const int k1 = (it + 1) * BK;
            aR0 = *(const float4*)(xg + k1);
            aR1 = *(const float4*)(xg + k1 + 4);
            const float* wgk = wg + (size_t)k1 * OUTDIM;
            bR0 = *(const float4*)(wgk);
            bR1 = *(const float4*)(wgk + 4);
        }

        const uint32_t Ab = As_base + buf * A_BUF_BYTES;
        const uint32_t Bb = Bs_base + buf * B_BUF_BYTES;

        #pragma unroll
        for (int s = 0; s < 2; ++s) {
            uint32_t af[2][4], bf[4];
            ldmatrix_x4(af[0], Ab + a_off[0][s]);
            ldmatrix_x4(af[1], Ab + a_off[1][s]);
            ldmatrix_x4_trans(bf, Bb + b_off[s]);
            #pragma unroll
            for (int mt = 0; mt < 2; ++mt) {
                mma_bf16(acc[mt][0], af[mt], bf[0], bf[1]);
                mma_bf16(acc[mt][1], af[mt], bf[2], bf[3]);
            }
        }

        if (it + 1 < NIT) {
            const int nbuf = (it + 1) & 1;
            pack_store16(&As[nbuf][arow * A_STRIDE + ak], aR0, aR1);
            pack_store16(&Bs[nbuf][brow * B_STRIDE + bno], bR0, bR1);
            __syncthreads();
        }
    }

    // write bf16 partials
    __nv_bfloat16* pg = g_part[kz];
    const int crow = lane >> 2;
    const int ccol = (lane & 3) << 1;
    #pragma unroll
    for (int nt = 0; nt < 2; ++nt) {
        const int col = n0 + wn * 16 + nt * 8 + ccol;
        #pragma unroll
        for (int mt = 0; mt < 2; ++mt) {
            const int row0 = m0 + wm * 32 + mt * 16 + crow;
            *reinterpret_cast<uint32_t*>(&pg[(size_t)row0 * OUTDIM + col]) =
                pack_bf2(acc[mt][nt][0], acc[mt][nt][1]);
            *reinterpret_cast<uint32_t*>(&pg[(size_t)(row0 + 8) * OUTDIM + col]) =
                pack_bf2(acc[mt][nt][2], acc[mt][nt][3]);
        }
    }
}

// ---------------------------------------------------------------------------
// Kernel 2: reduce bf16 partials + bias, mean, sigmoid. PDL-gated.
// grid = 256 x 256 thr, one float4 output per thread.
// ---------------------------------------------------------------------------
__global__ void __launch_bounds__(256) epilogue_kernel(float* __restrict__ out) {
    // launched early via PDL; wait for the GEMM grid's memory to be visible
    pdl_wait();

    const int i4  = blockIdx.x * 256 + threadIdx.x;   // float4 index
    const int idx = i4 << 2;                          // element index
    const int o   = idx & (OUTDIM - 1);

    uint2 pu[KSPLIT];
    #pragma unroll
    for (int k = 0; k < KSPLIT; ++k)
        pu[k] = __ldcg(reinterpret_cast<const uint2*>(&g_part[k][idx]));

    float4 bb[KSPLIT];
    #pragma unroll
    for (int k = 0; k < KSPLIT; ++k)
        bb[k] = __ldg(reinterpret_cast<const float4*>(&g_bias_part[k][o]));

    float4 s = make_float4(0.f, 0.f, 0.f, 0.f);
    #pragma unroll
    for (int k = 0; k < KSPLIT; ++k) {
        float2 lo = __bfloat1622float2(*reinterpret_cast<__nv_bfloat162*>(&pu[k].x));
        float2 hi = __bfloat1622float2(*reinterpret_cast<__nv_bfloat162*>(&pu[k].y));
        s.x += lo.x + bb[k].x;
        s.y += lo.y + bb[k].y;
        s.z += hi.x + bb[k].z;
        s.w += hi.y + bb[k].w;
    }

    const float inv = 1.0f / (float)INDIM;
    float4 r;
    r.x = sigmoidf_(s.x * inv);
    r.y = sigmoidf_(s.y * inv);
    r.z = sigmoidf_(s.z * inv);
    r.w = sigmoidf_(s.w * inv);
    reinterpret_cast<float4*>(out)[i4] = r;
}

// ---------------------------------------------------------------------------
extern "C" void kernel_launch(void* const* d_in, const int* in_sizes, int n_in,
                              void* d_out, int out_size) {
    const float* x    = (const float*)d_in[0];
    const float* wgt  = (const float*)d_in[1];
    const float* bias = (const float*)d_in[2];
    float* out        = (float*)d_out;
    (void)in_sizes; (void)n_in; (void)out_size;

    dim3 g1(OUTDIM / BN, BATCH / BM + 1, KSPLIT);   // (16, 5, 4) = 320 CTAs
    gemm_splitk_kernel<<<g1, 256>>>(x, wgt, bias);

    // epilogue with programmatic dependent launch (overlap launch/ramp)
    cudaLaunchConfig_t cfg = {};
    cfg.gridDim  = dim3(256, 1, 1);
    cfg.blockDim = dim3(256, 1, 1);
    cfg.dynamicSmemBytes = 0;
    cfg.stream = 0;
    cudaLaunchAttribute attr[1];
    attr[0].id = cudaLaunchAttributeProgrammaticStreamSerialization;
    attr[0].val.programmaticStreamSerializationAllowed = 1;
    cfg.attrs = attr;
    cfg.numAttrs = 1;
    cudaLaunchKernelEx(&cfg, epilogue_kernel, out);
}